// round 1
// baseline (speedup 1.0000x reference)
#include <cuda_runtime.h>
#include <cstdint>

#define GAMMA_C 0.2f
#define ALPHA_C 0.6f

// Per-element focal BCE-with-logits loss, numerically stable, 3 MUFU ops:
//   p = sigmoid(x)
//   logsig(x)  = min(x,0)  - log(1 + exp(-|x|))   [= log p]
//   logsig(-x) = min(-x,0) - log(1 + exp(-|x|))   [= log(1-p)]
//   target==1: -ALPHA     * (1-p)^g * log p     = -ALPHA     * exp(g*logsig(-x)) * logsig(x)
//   target!=1: -(1-ALPHA) * p^g     * log(1-p)  = -(1-ALPHA) * exp(g*logsig(x))  * logsig(-x)
__device__ __forceinline__ float focal_elem(float x, int t) {
    float e  = __expf(-fabsf(x));          // MUFU 1 (EX2)
    float L  = __logf(1.0f + e);           // MUFU 2 (LG2)
    float ls_x  = fminf(x, 0.0f) - L;      // log p
    float ls_mx = fminf(-x, 0.0f) - L;     // log (1-p)
    bool  pos = (t == 1);
    float a = pos ? ls_mx : ls_x;          // goes inside the power
    float b = pos ? ls_x  : ls_mx;         // the log term
    float c = pos ? ALPHA_C : (1.0f - ALPHA_C);
    return -c * __expf(GAMMA_C * a) * b;   // MUFU 3 (EX2)
}

__global__ void focal_bce_mean_kernel(const float4* __restrict__ logits4,
                                      const int4* __restrict__ target4,
                                      const float* __restrict__ logits,
                                      const int* __restrict__ target,
                                      float* __restrict__ out,
                                      int n_vec, int n_total, float inv_total) {
    float acc = 0.0f;
    int idx = blockIdx.x * blockDim.x + threadIdx.x;
    int stride = gridDim.x * blockDim.x;

    for (int i = idx; i < n_vec; i += stride) {
        float4 x = logits4[i];
        int4   t = target4[i];
        acc += focal_elem(x.x, t.x);
        acc += focal_elem(x.y, t.y);
        acc += focal_elem(x.z, t.z);
        acc += focal_elem(x.w, t.w);
    }

    // Scalar tail (n_total may not be divisible by 4; here it is, but be safe).
    int tail_start = n_vec * 4;
    for (int i = tail_start + idx; i < n_total; i += stride) {
        acc += focal_elem(logits[i], target[i]);
    }

    // Warp reduce
    #pragma unroll
    for (int o = 16; o > 0; o >>= 1)
        acc += __shfl_xor_sync(0xFFFFFFFF, acc, o);

    // Block reduce
    __shared__ float smem[32];
    int lane = threadIdx.x & 31;
    int wid  = threadIdx.x >> 5;
    if (lane == 0) smem[wid] = acc;
    __syncthreads();
    if (wid == 0) {
        int nwarps = (blockDim.x + 31) >> 5;
        float v = (lane < nwarps) ? smem[lane] : 0.0f;
        #pragma unroll
        for (int o = 16; o > 0; o >>= 1)
            v += __shfl_xor_sync(0xFFFFFFFF, v, o);
        if (lane == 0)
            atomicAdd(out, v * inv_total);
    }
}

extern "C" void kernel_launch(void* const* d_in, const int* in_sizes, int n_in,
                              void* d_out, int out_size) {
    const float* logits = (const float*)d_in[0];
    const int*   target = (const int*)d_in[1];
    float*       out    = (float*)d_out;

    int n_total = in_sizes[0];
    int n_vec   = n_total >> 2;
    float inv_total = 1.0f / (float)n_total;

    // d_out is poisoned; zero the scalar accumulator (async memset is
    // graph-capturable).
    cudaMemsetAsync(d_out, 0, sizeof(float), 0);

    const int threads = 256;
    // 148 SMs x 8 blocks x 256 threads = full residency; each thread does
    // ~35 float4 iterations -> plenty of MLP.
    int blocks = 148 * 8;
    int max_blocks = (n_vec + threads - 1) / threads;
    if (blocks > max_blocks && max_blocks > 0) blocks = max_blocks;
    if (blocks < 1) blocks = 1;

    focal_bce_mean_kernel<<<blocks, threads>>>(
        (const float4*)logits, (const int4*)target,
        logits, target, out, n_vec, n_total, inv_total);
}